// round 10
// baseline (speedup 1.0000x reference)
#include <cuda_runtime.h>
#include <cuda_bf16.h>
#include <cstdint>

// ---------------------------------------------------------------------------
// GCN: out = relu(Anorm (relu(Anorm (X W1) + b1)) W2 + b2) Wl + bl
// Anorm = D^-1/2 (A + I) D^-1/2, deg over dst incl self-loop.
// Strategy: y = dinv .* (X@W)  (GEMM epilogue),
//           h = relu(dinv .* (sum_{nb} y[src] + y[self]) + b)  (CSR agg, warp/node)
// ---------------------------------------------------------------------------

#define NMAX 100000
#define EMAX 1600000

__device__ float g_y[(size_t)NMAX * 128];
__device__ float g_h[(size_t)NMAX * 128];
__device__ int   g_cnt[NMAX];
__device__ int   g_cur[NMAX];
__device__ int   g_off[NMAX + 1];
__device__ float g_dinv[NMAX];
__device__ int   g_esrc[EMAX];
__device__ int   g_bsum[512];
__device__ int   g_bbase[512];

// ---------------- packed f32x2 helpers (ptxas won't auto-fuse FFMA2) -------
__device__ __forceinline__ unsigned long long pack2(float x, float y) {
    unsigned long long r;
    asm("mov.b64 %0, {%1, %2};" : "=l"(r)
        : "r"(__float_as_uint(x)), "r"(__float_as_uint(y)));
    return r;
}
__device__ __forceinline__ void ffma2(unsigned long long& c,
                                      unsigned long long a,
                                      unsigned long long b) {
    asm("fma.rn.f32x2 %0, %1, %2, %0;" : "+l"(c) : "l"(a), "l"(b));
}
__device__ __forceinline__ float2 unpack2(unsigned long long v) {
    unsigned lo, hi;
    asm("mov.b64 {%0, %1}, %2;" : "=r"(lo), "=r"(hi) : "l"(v));
    return make_float2(__uint_as_float(lo), __uint_as_float(hi));
}

// ---------------- setup kernels --------------------------------------------
__global__ void k_init(int n) {
    int i = blockIdx.x * blockDim.x + threadIdx.x;
    if (i < n) { g_cnt[i] = 0; g_cur[i] = 0; }
}

__global__ void k_count(const int* __restrict__ dst, int E) {
    int stride = gridDim.x * blockDim.x;
    for (int e = blockIdx.x * blockDim.x + threadIdx.x; e < E; e += stride)
        atomicAdd(&g_cnt[dst[e]], 1);
}

__global__ void k_bsum(int n) {
    __shared__ int s[256];
    int t = threadIdx.x;
    int i = blockIdx.x * 256 + t;
    s[t] = (i < n) ? g_cnt[i] : 0;
    __syncthreads();
    for (int o = 128; o > 0; o >>= 1) {
        if (t < o) s[t] += s[t + o];
        __syncthreads();
    }
    if (t == 0) g_bsum[blockIdx.x] = s[0];
}

__global__ void k_bscan(int nb, int n) {
    __shared__ int s[512];
    int t = threadIdx.x;
    int v = (t < nb) ? g_bsum[t] : 0;
    s[t] = v;
    __syncthreads();
    for (int o = 1; o < 512; o <<= 1) {
        int x = (t >= o) ? s[t - o] : 0;
        __syncthreads();
        s[t] += x;
        __syncthreads();
    }
    if (t < nb) g_bbase[t] = s[t] - v;
    if (t == 511) g_off[n] = s[511];
}

__global__ void k_scan3(int n) {
    __shared__ int s[256];
    int t = threadIdx.x;
    int i = blockIdx.x * 256 + t;
    int v = (i < n) ? g_cnt[i] : 0;
    s[t] = v;
    __syncthreads();
    for (int o = 1; o < 256; o <<= 1) {
        int x = (t >= o) ? s[t - o] : 0;
        __syncthreads();
        s[t] += x;
        __syncthreads();
    }
    if (i < n) {
        g_off[i]  = g_bbase[blockIdx.x] + s[t] - v;
        g_dinv[i] = rsqrtf((float)(v + 1));
    }
}

__global__ void k_fill(const int* __restrict__ src, const int* __restrict__ dst, int E) {
    int stride = gridDim.x * blockDim.x;
    for (int e = blockIdx.x * blockDim.x + threadIdx.x; e < E; e += stride) {
        int d = dst[e];
        int p = g_off[d] + atomicAdd(&g_cur[d], 1);
        g_esrc[p] = src[e];
    }
}

// ---------------- dense GEMM: C[M,128] = A[M,128] @ W[128,128], row-scaled --
template <bool SCALE>
__global__ __launch_bounds__(256, 2)
void gemm_nk128(const float* __restrict__ A, const float* __restrict__ W,
                const float* __restrict__ dinv, float* __restrict__ C, int M) {
    __shared__ float As[128][33];   // [row][k], pad -> conflict-free loads/stores
    __shared__ float Bs[32][128];   // [k][n]

    const int t  = threadIdx.x;
    const int tx = t & 15;          // 16 col-threads * 8 cols
    const int ty = t >> 4;          // 16 row-threads * 8 rows
    const int row0 = blockIdx.x * 128;

    const int la_r = t >> 3;            // 0..31
    const int la_c = (t & 7) * 4;       // 0..28
    const int lb_k = t >> 5;            // 0..7
    const int lb_c = (t & 31) * 4;      // 0..124

    unsigned long long c2[8][4];
#pragma unroll
    for (int i = 0; i < 8; ++i)
#pragma unroll
        for (int j = 0; j < 4; ++j) c2[i][j] = 0ULL;

    for (int kb = 0; kb < 4; ++kb) {
#pragma unroll
        for (int p = 0; p < 4; ++p) {
            int r = p * 32 + la_r;
            int grow = row0 + r;
            float4 v = make_float4(0.f, 0.f, 0.f, 0.f);
            if (grow < M)
                v = *(const float4*)&A[(size_t)grow * 128 + kb * 32 + la_c];
            As[r][la_c + 0] = v.x; As[r][la_c + 1] = v.y;
            As[r][la_c + 2] = v.z; As[r][la_c + 3] = v.w;
        }
#pragma unroll
        for (int p = 0; p < 4; ++p) {
            int kk = p * 8 + lb_k;
            *(float4*)&Bs[kk][lb_c] =
                *(const float4*)&W[(size_t)(kb * 32 + kk) * 128 + lb_c];
        }
        __syncthreads();

#pragma unroll 8
        for (int k = 0; k < 32; ++k) {
            unsigned long long b2[4];
#pragma unroll
            for (int j = 0; j < 4; ++j)
                b2[j] = *(const unsigned long long*)&Bs[k][tx * 8 + 2 * j];
#pragma unroll
            for (int i = 0; i < 8; ++i) {
                float a = As[ty * 8 + i][k];
                unsigned long long ad = pack2(a, a);
#pragma unroll
                for (int j = 0; j < 4; ++j) ffma2(c2[i][j], ad, b2[j]);
            }
        }
        __syncthreads();
    }

#pragma unroll
    for (int i = 0; i < 8; ++i) {
        int row = row0 + ty * 8 + i;
        if (row < M) {
            float s = SCALE ? dinv[row] : 1.f;
            float o[8];
#pragma unroll
            for (int j = 0; j < 4; ++j) {
                float2 v = unpack2(c2[i][j]);
                o[2 * j] = v.x * s; o[2 * j + 1] = v.y * s;
            }
            float4* cp = (float4*)&C[(size_t)row * 128 + tx * 8];
            cp[0] = make_float4(o[0], o[1], o[2], o[3]);
            cp[1] = make_float4(o[4], o[5], o[6], o[7]);
        }
    }
}

// ---------------- aggregation: h = relu(dinv*(sum y[src] + y[self]) + b) ---
__global__ void agg_kernel(const float* __restrict__ y,
                           const float* __restrict__ dinv,
                           const float* __restrict__ bias,
                           float* __restrict__ h, int n) {
    const int lane = threadIdx.x & 31;
    const int warp = (blockIdx.x * blockDim.x + threadIdx.x) >> 5;
    const int nwarps = (gridDim.x * blockDim.x) >> 5;
    const float4* yv = (const float4*)y;
    float4* hv = (float4*)h;
    const float4 bv = *(const float4*)&bias[lane * 4];

    for (int node = warp; node < n; node += nwarps) {
        float4 a0 = yv[(size_t)node * 32 + lane];  // self-loop contribution
        float4 a1 = make_float4(0.f, 0.f, 0.f, 0.f);
        int p = g_off[node], pe = g_off[node + 1];
        for (; p + 2 <= pe; p += 2) {
            int s0 = g_esrc[p], s1 = g_esrc[p + 1];
            float4 v0 = yv[(size_t)s0 * 32 + lane];
            float4 v1 = yv[(size_t)s1 * 32 + lane];
            a0.x += v0.x; a0.y += v0.y; a0.z += v0.z; a0.w += v0.w;
            a1.x += v1.x; a1.y += v1.y; a1.z += v1.z; a1.w += v1.w;
        }
        if (p < pe) {
            int s0 = g_esrc[p];
            float4 v0 = yv[(size_t)s0 * 32 + lane];
            a0.x += v0.x; a0.y += v0.y; a0.z += v0.z; a0.w += v0.w;
        }
        float d = dinv[node];
        float4 r;
        r.x = fmaxf(fmaf(a0.x + a1.x, d, bv.x), 0.f);
        r.y = fmaxf(fmaf(a0.y + a1.y, d, bv.y), 0.f);
        r.z = fmaxf(fmaf(a0.z + a1.z, d, bv.z), 0.f);
        r.w = fmaxf(fmaf(a0.w + a1.w, d, bv.w), 0.f);
        hv[(size_t)node * 32 + lane] = r;
    }
}

// ---------------- classifier: C[M,40] = A[M,128] @ Wl[128,40] + bl ---------
__global__ __launch_bounds__(256, 2)
void gemm_cls(const float* __restrict__ A, const float* __restrict__ W,
              const float* __restrict__ bias, float* __restrict__ C, int M) {
    __shared__ float As[128][33];
    __shared__ float Ws[32][40];

    const int t  = threadIdx.x;
    const int tx = t & 7;    // 8 col-threads * 5 cols
    const int ty = t >> 3;   // 32 row-threads * 4 rows
    const int row0 = blockIdx.x * 128;
    const int la_r = t >> 3;
    const int la_c = (t & 7) * 4;

    unsigned long long c2[2][5];
#pragma unroll
    for (int i = 0; i < 2; ++i)
#pragma unroll
        for (int c = 0; c < 5; ++c) c2[i][c] = 0ULL;

    for (int kb = 0; kb < 4; ++kb) {
#pragma unroll
        for (int p = 0; p < 4; ++p) {
            int r = p * 32 + la_r;
            int grow = row0 + r;
            float4 v = make_float4(0.f, 0.f, 0.f, 0.f);
            if (grow < M)
                v = *(const float4*)&A[(size_t)grow * 128 + kb * 32 + la_c];
            As[r][la_c + 0] = v.x; As[r][la_c + 1] = v.y;
            As[r][la_c + 2] = v.z; As[r][la_c + 3] = v.w;
        }
        for (int idx = t; idx < 32 * 40; idx += 256) {
            int rr = idx / 40, cc = idx % 40;
            Ws[rr][cc] = W[(size_t)(kb * 32 + rr) * 40 + cc];
        }
        __syncthreads();

#pragma unroll 8
        for (int k = 0; k < 32; ++k) {
            float a0 = As[ty * 4 + 0][k];
            float a1 = As[ty * 4 + 1][k];
            float a2 = As[ty * 4 + 2][k];
            float a3 = As[ty * 4 + 3][k];
            unsigned long long A01 = pack2(a0, a1);
            unsigned long long A23 = pack2(a2, a3);
#pragma unroll
            for (int c = 0; c < 5; ++c) {
                float b = Ws[k][tx * 5 + c];
                unsigned long long bd = pack2(b, b);
                ffma2(c2[0][c], A01, bd);
                ffma2(c2[1][c], A23, bd);
            }
        }
        __syncthreads();
    }

#pragma unroll
    for (int ip = 0; ip < 2; ++ip)
#pragma unroll
        for (int c = 0; c < 5; ++c) {
            float2 v = unpack2(c2[ip][c]);
            int col = tx * 5 + c;
            float bb = bias[col];
            int r0 = row0 + ty * 4 + 2 * ip;
            if (r0 < M)     C[(size_t)r0 * 40 + col] = v.x + bb;
            if (r0 + 1 < M) C[(size_t)(r0 + 1) * 40 + col] = v.y + bb;
        }
}

// ---------------------------------------------------------------------------
extern "C" void kernel_launch(void* const* d_in, const int* in_sizes, int n_in,
                              void* d_out, int out_size) {
    const float* X  = (const float*)d_in[0];
    const int*   EI = (const int*)d_in[1];
    const float* W1 = (const float*)d_in[2];
    const float* b1 = (const float*)d_in[3];
    const float* W2 = (const float*)d_in[4];
    const float* b2 = (const float*)d_in[5];
    const float* Wl = (const float*)d_in[6];
    const float* bl = (const float*)d_in[7];
    float* out = (float*)d_out;

    const int N = in_sizes[0] / 128;
    const int E = in_sizes[1] / 2;
    const int* src = EI;
    const int* dst = EI + E;

    void* p;
    cudaGetSymbolAddress(&p, g_y);    float* y    = (float*)p;
    cudaGetSymbolAddress(&p, g_h);    float* h    = (float*)p;
    cudaGetSymbolAddress(&p, g_dinv); float* dinv = (float*)p;

    const int nb = (N + 255) / 256;        // 391 (<= 512 for single-block scan)
    const int gt = (N + 127) / 128;        // 782 GEMM tiles
    const int SCAT_BLOCKS = 1184;          // 148 SMs * 8

    // ---- build dinv + CSR (by dst) once ----
    k_init<<<nb, 256>>>(N);
    k_count<<<SCAT_BLOCKS, 256>>>(dst, E);
    k_bsum<<<nb, 256>>>(N);
    k_bscan<<<1, 512>>>(nb, N);
    k_scan3<<<nb, 256>>>(N);
    k_fill<<<SCAT_BLOCKS, 256>>>(src, dst, E);

    // ---- layer 1 ----
    gemm_nk128<true><<<gt, 256>>>(X, W1, dinv, y, N);
    agg_kernel<<<SCAT_BLOCKS, 256>>>(y, dinv, b1, h, N);
    // ---- layer 2 ----
    gemm_nk128<true><<<gt, 256>>>(h, W2, dinv, y, N);
    agg_kernel<<<SCAT_BLOCKS, 256>>>(y, dinv, b2, h, N);
    // ---- classifier ----
    gemm_cls<<<gt, 256>>>(h, Wl, bl, out, N);
}

// round 11
// speedup vs baseline: 1.0064x; 1.0064x over previous
#include <cuda_runtime.h>
#include <cuda_bf16.h>
#include <cstdint>

// ---------------------------------------------------------------------------
// GCN: out = relu(Anorm (relu(Anorm (X W1) + b1)) W2 + b2) Wl + bl
// Anorm = D^-1/2 (A + I) D^-1/2, deg over dst incl self-loop.
// Strategy: y = dinv .* (X@W)  (GEMM epilogue),
//           h = relu(dinv .* (sum_{nb} y[src] + y[self]) + b)  (CSR agg, warp/node)
// ---------------------------------------------------------------------------

#define NMAX 100000
#define EMAX 1600000

__device__ float g_y[(size_t)NMAX * 128];
__device__ float g_h[(size_t)NMAX * 128];
__device__ int   g_cnt[NMAX];
__device__ int   g_cur[NMAX];
__device__ int   g_off[NMAX + 1];
__device__ float g_dinv[NMAX];
__device__ int   g_esrc[EMAX];
__device__ int   g_bsum[512];
__device__ int   g_bbase[512];

// ---------------- packed f32x2 helpers (ptxas won't auto-fuse FFMA2) -------
__device__ __forceinline__ unsigned long long pack2(float x, float y) {
    unsigned long long r;
    asm("mov.b64 %0, {%1, %2};" : "=l"(r)
        : "r"(__float_as_uint(x)), "r"(__float_as_uint(y)));
    return r;
}
__device__ __forceinline__ void ffma2(unsigned long long& c,
                                      unsigned long long a,
                                      unsigned long long b) {
    asm("fma.rn.f32x2 %0, %1, %2, %0;" : "+l"(c) : "l"(a), "l"(b));
}
__device__ __forceinline__ float2 unpack2(unsigned long long v) {
    unsigned lo, hi;
    asm("mov.b64 {%0, %1}, %2;" : "=r"(lo), "=r"(hi) : "l"(v));
    return make_float2(__uint_as_float(lo), __uint_as_float(hi));
}

// ---------------- setup kernels --------------------------------------------
__global__ void k_init(int n) {
    int i = blockIdx.x * blockDim.x + threadIdx.x;
    if (i < n) { g_cnt[i] = 0; g_cur[i] = 0; }
}

__global__ void k_count(const int* __restrict__ dst, int E) {
    int stride = gridDim.x * blockDim.x;
    for (int e = blockIdx.x * blockDim.x + threadIdx.x; e < E; e += stride)
        atomicAdd(&g_cnt[dst[e]], 1);
}

__global__ void k_bsum(int n) {
    __shared__ int s[256];
    int t = threadIdx.x;
    int i = blockIdx.x * 256 + t;
    s[t] = (i < n) ? g_cnt[i] : 0;
    __syncthreads();
    for (int o = 128; o > 0; o >>= 1) {
        if (t < o) s[t] += s[t + o];
        __syncthreads();
    }
    if (t == 0) g_bsum[blockIdx.x] = s[0];
}

__global__ void k_bscan(int nb, int n) {
    __shared__ int s[512];
    int t = threadIdx.x;
    int v = (t < nb) ? g_bsum[t] : 0;
    s[t] = v;
    __syncthreads();
    for (int o = 1; o < 512; o <<= 1) {
        int x = (t >= o) ? s[t - o] : 0;
        __syncthreads();
        s[t] += x;
        __syncthreads();
    }
    if (t < nb) g_bbase[t] = s[t] - v;
    if (t == 511) g_off[n] = s[511];
}

__global__ void k_scan3(int n) {
    __shared__ int s[256];
    int t = threadIdx.x;
    int i = blockIdx.x * 256 + t;
    int v = (i < n) ? g_cnt[i] : 0;
    s[t] = v;
    __syncthreads();
    for (int o = 1; o < 256; o <<= 1) {
        int x = (t >= o) ? s[t - o] : 0;
        __syncthreads();
        s[t] += x;
        __syncthreads();
    }
    if (i < n) {
        g_off[i]  = g_bbase[blockIdx.x] + s[t] - v;
        g_dinv[i] = rsqrtf((float)(v + 1));
    }
}

__global__ void k_fill(const int* __restrict__ src, const int* __restrict__ dst, int E) {
    int stride = gridDim.x * blockDim.x;
    for (int e = blockIdx.x * blockDim.x + threadIdx.x; e < E; e += stride) {
        int d = dst[e];
        int p = g_off[d] + atomicAdd(&g_cur[d], 1);
        g_esrc[p] = src[e];
    }
}

// ---------------- dense GEMM: C[M,128] = A[M,128] @ W[128,128], row-scaled --
template <bool SCALE>
__global__ __launch_bounds__(256, 2)
void gemm_nk128(const float* __restrict__ A, const float* __restrict__ W,
                const float* __restrict__ dinv, float* __restrict__ C, int M) {
    __shared__ float As[128][33];   // [row][k], pad -> conflict-free loads/stores
    __shared__ float Bs[32][128];   // [k][n]

    const int t  = threadIdx.x;
    const int tx = t & 15;          // 16 col-threads * 8 cols
    const int ty = t >> 4;          // 16 row-threads * 8 rows
    const int row0 = blockIdx.x * 128;

    const int la_r = t >> 3;            // 0..31
    const int la_c = (t & 7) * 4;       // 0..28
    const int lb_k = t >> 5;            // 0..7
    const int lb_c = (t & 31) * 4;      // 0..124

    unsigned long long c2[8][4];
#pragma unroll
    for (int i = 0; i < 8; ++i)
#pragma unroll
        for (int j = 0; j < 4; ++j) c2[i][j] = 0ULL;

    for (int kb = 0; kb < 4; ++kb) {
#pragma unroll
        for (int p = 0; p < 4; ++p) {
            int r = p * 32 + la_r;
            int grow = row0 + r;
            float4 v = make_float4(0.f, 0.f, 0.f, 0.f);
            if (grow < M)
                v = *(const float4*)&A[(size_t)grow * 128 + kb * 32 + la_c];
            As[r][la_c + 0] = v.x; As[r][la_c + 1] = v.y;
            As[r][la_c + 2] = v.z; As[r][la_c + 3] = v.w;
        }
#pragma unroll
        for (int p = 0; p < 4; ++p) {
            int kk = p * 8 + lb_k;
            *(float4*)&Bs[kk][lb_c] =
                *(const float4*)&W[(size_t)(kb * 32 + kk) * 128 + lb_c];
        }
        __syncthreads();

#pragma unroll 8
        for (int k = 0; k < 32; ++k) {
            unsigned long long b2[4];
#pragma unroll
            for (int j = 0; j < 4; ++j)
                b2[j] = *(const unsigned long long*)&Bs[k][tx * 8 + 2 * j];
#pragma unroll
            for (int i = 0; i < 8; ++i) {
                float a = As[ty * 8 + i][k];
                unsigned long long ad = pack2(a, a);
#pragma unroll
                for (int j = 0; j < 4; ++j) ffma2(c2[i][j], ad, b2[j]);
            }
        }
        __syncthreads();
    }

#pragma unroll
    for (int i = 0; i < 8; ++i) {
        int row = row0 + ty * 8 + i;
        if (row < M) {
            float s = SCALE ? dinv[row] : 1.f;
            float o[8];
#pragma unroll
            for (int j = 0; j < 4; ++j) {
                float2 v = unpack2(c2[i][j]);
                o[2 * j] = v.x * s; o[2 * j + 1] = v.y * s;
            }
            float4* cp = (float4*)&C[(size_t)row * 128 + tx * 8];
            cp[0] = make_float4(o[0], o[1], o[2], o[3]);
            cp[1] = make_float4(o[4], o[5], o[6], o[7]);
        }
    }
}

// ---------------- aggregation: h = relu(dinv*(sum y[src] + y[self]) + b) ---
__global__ void agg_kernel(const float* __restrict__ y,
                           const float* __restrict__ dinv,
                           const float* __restrict__ bias,
                           float* __restrict__ h, int n) {
    const int lane = threadIdx.x & 31;
    const int warp = (blockIdx.x * blockDim.x + threadIdx.x) >> 5;
    const int nwarps = (gridDim.x * blockDim.x) >> 5;
    const float4* yv = (const float4*)y;
    float4* hv = (float4*)h;
    const float4 bv = *(const float4*)&bias[lane * 4];

    for (int node = warp; node < n; node += nwarps) {
        float4 a0 = yv[(size_t)node * 32 + lane];  // self-loop contribution
        float4 a1 = make_float4(0.f, 0.f, 0.f, 0.f);
        int p = g_off[node], pe = g_off[node + 1];
        for (; p + 2 <= pe; p += 2) {
            int s0 = g_esrc[p], s1 = g_esrc[p + 1];
            float4 v0 = yv[(size_t)s0 * 32 + lane];
            float4 v1 = yv[(size_t)s1 * 32 + lane];
            a0.x += v0.x; a0.y += v0.y; a0.z += v0.z; a0.w += v0.w;
            a1.x += v1.x; a1.y += v1.y; a1.z += v1.z; a1.w += v1.w;
        }
        if (p < pe) {
            int s0 = g_esrc[p];
            float4 v0 = yv[(size_t)s0 * 32 + lane];
            a0.x += v0.x; a0.y += v0.y; a0.z += v0.z; a0.w += v0.w;
        }
        float d = dinv[node];
        float4 r;
        r.x = fmaxf(fmaf(a0.x + a1.x, d, bv.x), 0.f);
        r.y = fmaxf(fmaf(a0.y + a1.y, d, bv.y), 0.f);
        r.z = fmaxf(fmaf(a0.z + a1.z, d, bv.z), 0.f);
        r.w = fmaxf(fmaf(a0.w + a1.w, d, bv.w), 0.f);
        hv[(size_t)node * 32 + lane] = r;
    }
}

// ---------------- classifier: C[M,40] = A[M,128] @ Wl[128,40] + bl ---------
__global__ __launch_bounds__(256, 2)
void gemm_cls(const float* __restrict__ A, const float* __restrict__ W,
              const float* __restrict__ bias, float* __restrict__ C, int M) {
    __shared__ float As[128][33];
    __shared__ float Ws[32][40];

    const int t  = threadIdx.x;
    const int tx = t & 7;    // 8 col-threads * 5 cols
    const int ty = t >> 3;   // 32 row-threads * 4 rows
    const int row0 = blockIdx.x * 128;
    const int la_r = t >> 3;
    const int la_c = (t & 7) * 4;

    unsigned long long c2[2][5];
#pragma unroll
    for (int i = 0; i < 2; ++i)
#pragma unroll
        for (int c = 0; c < 5; ++c) c2[i][c] = 0ULL;

    for (int kb = 0; kb < 4; ++kb) {
#pragma unroll
        for (int p = 0; p < 4; ++p) {
            int r = p * 32 + la_r;
            int grow = row0 + r;
            float4 v = make_float4(0.f, 0.f, 0.f, 0.f);
            if (grow < M)
                v = *(const float4*)&A[(size_t)grow * 128 + kb * 32 + la_c];
            As[r][la_c + 0] = v.x; As[r][la_c + 1] = v.y;
            As[r][la_c + 2] = v.z; As[r][la_c + 3] = v.w;
        }
        for (int idx = t; idx < 32 * 40; idx += 256) {
            int rr = idx / 40, cc = idx % 40;
            Ws[rr][cc] = W[(size_t)(kb * 32 + rr) * 40 + cc];
        }
        __syncthreads();

#pragma unroll 8
        for (int k = 0; k < 32; ++k) {
            float a0 = As[ty * 4 + 0][k];
            float a1 = As[ty * 4 + 1][k];
            float a2 = As[ty * 4 + 2][k];
            float a3 = As[ty * 4 + 3][k];
            unsigned long long A01 = pack2(a0, a1);
            unsigned long long A23 = pack2(a2, a3);
#pragma unroll
            for (int c = 0; c < 5; ++c) {
                float b = Ws[k][tx * 5 + c];
                unsigned long long bd = pack2(b, b);
                ffma2(c2[0][c], A01, bd);
                ffma2(c2[1][c], A23, bd);
            }
        }
        __syncthreads();
    }

#pragma unroll
    for (int ip = 0; ip < 2; ++ip)
#pragma unroll
        for (int c = 0; c < 5; ++c) {
            float2 v = unpack2(c2[ip][c]);
            int col = tx * 5 + c;
            float bb = bias[col];
            int r0 = row0 + ty * 4 + 2 * ip;
            if (r0 < M)     C[(size_t)r0 * 40 + col] = v.x + bb;
            if (r0 + 1 < M) C[(size_t)(r0 + 1) * 40 + col] = v.y + bb;
        }
}

// ---------------------------------------------------------------------------
extern "C" void kernel_launch(void* const* d_in, const int* in_sizes, int n_in,
                              void* d_out, int out_size) {
    const float* X  = (const float*)d_in[0];
    const int*   EI = (const int*)d_in[1];
    const float* W1 = (const float*)d_in[2];
    const float* b1 = (const float*)d_in[3];
    const float* W2 = (const float*)d_in[4];
    const float* b2 = (const float*)d_in[5];
    const float* Wl = (const float*)d_in[6];
    const float* bl = (const float*)d_in[7];
    float* out = (float*)d_out;

    const int N = in_sizes[0] / 128;
    const int E = in_sizes[1] / 2;
    const int* src = EI;
    const int* dst = EI + E;

    void* p;
    cudaGetSymbolAddress(&p, g_y);    float* y    = (float*)p;
    cudaGetSymbolAddress(&p, g_h);    float* h    = (float*)p;
    cudaGetSymbolAddress(&p, g_dinv); float* dinv = (float*)p;

    const int nb = (N + 255) / 256;        // 391 (<= 512 for single-block scan)
    const int gt = (N + 127) / 128;        // 782 GEMM tiles
    const int SCAT_BLOCKS = 1184;          // 148 SMs * 8

    // ---- build dinv + CSR (by dst) once ----
    k_init<<<nb, 256>>>(N);
    k_count<<<SCAT_BLOCKS, 256>>>(dst, E);
    k_bsum<<<nb, 256>>>(N);
    k_bscan<<<1, 512>>>(nb, N);
    k_scan3<<<nb, 256>>>(N);
    k_fill<<<SCAT_BLOCKS, 256>>>(src, dst, E);

    // ---- layer 1 ----
    gemm_nk128<true><<<gt, 256>>>(X, W1, dinv, y, N);
    agg_kernel<<<SCAT_BLOCKS, 256>>>(y, dinv, b1, h, N);
    // ---- layer 2 ----
    gemm_nk128<true><<<gt, 256>>>(h, W2, dinv, y, N);
    agg_kernel<<<SCAT_BLOCKS, 256>>>(y, dinv, b2, h, N);
    // ---- classifier ----
    gemm_cls<<<gt, 256>>>(h, Wl, bl, out, N);
}